// round 5
// baseline (speedup 1.0000x reference)
#include <cuda_runtime.h>
#include <cstdint>

// VoxelUnshuffle (strided): out[n, c*8 + i] = features[n*8 + i, c]  (8x32 transpose per voxel)
//
// Warp-per-2-voxels layout: thread g -> pair p = g>>5, lane j0 = g&31.
// Each thread produces output float4s {j0, j0+32} for voxels 2p and 2p+1:
//   c = j0>>1, ib = (j0&1)*4.
// Per thread: 16 independent scalar loads (MLP=16, front-batched), 4 float4 stores.
// Per warp: reads 16 x 128B full lines, writes 4 contiguous 512B bursts
// (the pair's 2KB output region is fully contiguous). No cross-warp sharing.

__global__ void __launch_bounds__(256)
voxel_unshuffle_fused(const float* __restrict__ in, float4* __restrict__ out,
                      long long feat_threads,   // pair range rounded to blocks
                      long long n_pair_thr,     // exact ceil(n_vox/2) * 32
                      long long n_vox,
                      const int4* __restrict__ idx_src, float4* __restrict__ idx_dst,
                      long long n_idx4)
{
    long long g = (long long)blockIdx.x * blockDim.x + threadIdx.x;

    if (g < feat_threads) {
        if (g >= n_pair_thr) return;
        long long p  = g >> 5;
        int j0       = (int)(g & 31);
        int c        = j0 >> 1;
        int ib       = (j0 & 1) << 2;   // 0 or 4
        long long n0 = p << 1;
        bool has2    = (n0 + 1) < n_vox;

        const float* base0 = in + n0 * 256 + (long long)ib * 32 + c;
        const float* base1 = base0 + 256;

        float4 a, b, e, f;
        a.x = __ldg(base0 +   0);
        a.y = __ldg(base0 +  32);
        a.z = __ldg(base0 +  64);
        a.w = __ldg(base0 +  96);
        b.x = __ldg(base0 +  16);
        b.y = __ldg(base0 +  48);
        b.z = __ldg(base0 +  80);
        b.w = __ldg(base0 + 112);
        if (has2) {
            e.x = __ldg(base1 +   0);
            e.y = __ldg(base1 +  32);
            e.z = __ldg(base1 +  64);
            e.w = __ldg(base1 +  96);
            f.x = __ldg(base1 +  16);
            f.y = __ldg(base1 +  48);
            f.z = __ldg(base1 +  80);
            f.w = __ldg(base1 + 112);
        }

        float4* o = out + n0 * 64 + j0;
        asm volatile("st.global.cs.v4.f32 [%0], {%1,%2,%3,%4};"
                     :: "l"(o), "f"(a.x), "f"(a.y), "f"(a.z), "f"(a.w));
        asm volatile("st.global.cs.v4.f32 [%0], {%1,%2,%3,%4};"
                     :: "l"(o + 32), "f"(b.x), "f"(b.y), "f"(b.z), "f"(b.w));
        if (has2) {
            asm volatile("st.global.cs.v4.f32 [%0], {%1,%2,%3,%4};"
                         :: "l"(o + 64), "f"(e.x), "f"(e.y), "f"(e.z), "f"(e.w));
            asm volatile("st.global.cs.v4.f32 [%0], {%1,%2,%3,%4};"
                         :: "l"(o + 96), "f"(f.x), "f"(f.y), "f"(f.z), "f"(f.w));
        }
    } else {
        long long k = g - feat_threads;
        if (k >= n_idx4) return;
        int4 s = idx_src[k];
        float4 d;
        d.x = (float)s.x; d.y = (float)s.y; d.z = (float)s.z; d.w = (float)s.w;
        idx_dst[k] = d;
    }
}

extern "C" void kernel_launch(void* const* d_in, const int* in_sizes, int n_in,
                              void* d_out, int out_size)
{
    const float* features = (const float*)d_in[0];
    long long feat_elems  = (long long)in_sizes[0];      // 4,000,000 * 32
    long long n_vox       = feat_elems >> 8;             // 256 floats per voxel
    long long n_pairs     = (n_vox + 1) >> 1;
    long long n_pair_thr  = n_pairs * 32;                // one warp per voxel-pair

    long long n_idx4 = 0;
    const int4* idx_src = nullptr;
    float4* idx_dst = nullptr;
    if (n_in >= 2 && (long long)out_size > feat_elems) {
        long long tail      = (long long)out_size - feat_elems;
        long long idx_elems = (long long)in_sizes[1];
        long long n_copy    = tail < idx_elems ? tail : idx_elems;
        n_idx4  = n_copy >> 2;
        idx_src = (const int4*)d_in[1];
        idx_dst = (float4*)d_out + (feat_elems >> 2);
    }

    const int threads = 256;
    long long feat_blocks  = (n_pair_thr + threads - 1) / threads;
    long long feat_threads = feat_blocks * threads;
    long long idx_blocks   = (n_idx4 + threads - 1) / threads;
    long long blocks       = feat_blocks + idx_blocks;

    voxel_unshuffle_fused<<<(unsigned)blocks, threads>>>(
        features, (float4*)d_out, feat_threads, n_pair_thr, n_vox,
        idx_src, idx_dst, n_idx4);
}